// round 14
// baseline (speedup 1.0000x reference)
#include <cuda_runtime.h>
#include <cuda_fp16.h>
#include <cstdint>

// Problem constants (static per reference)
#define A_N    900      // anchors
#define P_N    13       // points
#define CAM_N  6        // cameras
#define LVL_N  4        // levels
#define CH     256      // channels
#define G_N    8        // groups (32 ch each)
#define SAMP   (P_N * CAM_N * LVL_N)   // 312 samples per anchor
#define THW    14960    // sum of H*W over levels
#define NWARP  16
#define FEAT_N (CAM_N * THW * CH)      // 22,978,560 elements

#define SPC    156                     // samples per work unit (half anchor)
#define UNITS  (A_N * 2)               // 1800 units
#define GRID_G 296                     // persistent gather CTAs (2/SM x 148)

__constant__ int c_H[LVL_N] = {64, 32, 16, 8};
__constant__ int c_W[LVL_N] = {176, 88, 44, 22};
__constant__ int c_S[LVL_N] = {0, 11264, 14080, 14784};

// fp16 feature copy + partials + queue/tickets (zero-init; reset in-kernel
// so every graph replay starts clean).
__device__ __half    d_feath[FEAT_N];
__device__ float     d_partial[2 * A_N * CH];
__device__ unsigned  d_qhead;
__device__ unsigned  d_done;
__device__ unsigned  d_ticket[A_N];

// ---------------- Kernel 1: fp32 -> fp16 feature conversion (R11) ----------
__global__ __launch_bounds__(256)
void cvt_kernel(const float* __restrict__ f)
{
    asm volatile("griddepcontrol.launch_dependents;" ::: "memory");
    const size_t i = ((size_t)blockIdx.x * 256 + threadIdx.x) * 8;
    const float4 a = __ldcs(reinterpret_cast<const float4*>(f + i));
    const float4 b = __ldcs(reinterpret_cast<const float4*>(f + i + 4));
    __half2 h[4];
    h[0] = __floats2half2_rn(a.x, a.y);
    h[1] = __floats2half2_rn(a.z, a.w);
    h[2] = __floats2half2_rn(b.x, b.y);
    h[3] = __floats2half2_rn(b.z, b.w);
    *reinterpret_cast<uint4*>(d_feath + i) = *reinterpret_cast<const uint4*>(h);
}

// One sample: bilinear combine in HFMA2 (pre-packed half2 corner weights),
// then fp32 FMA applies the group weight into the fp32 accumulator.
__device__ __forceinline__ void sample_acc(
    const uint4& u0, const uint4& u1, const uint4& u2, const uint4& u3,
    const uint4& cwp, const float wg, float2* acc)
{
    const __half2* c  = reinterpret_cast<const __half2*>(&cwp);
    const __half2* h0 = reinterpret_cast<const __half2*>(&u0);
    const __half2* h1 = reinterpret_cast<const __half2*>(&u1);
    const __half2* h2 = reinterpret_cast<const __half2*>(&u2);
    const __half2* h3 = reinterpret_cast<const __half2*>(&u3);
    #pragma unroll
    for (int j = 0; j < 4; j++) {
        __half2 v = __hmul2(c[0], h0[j]);
        v = __hfma2(c[1], h1[j], v);
        v = __hfma2(c[2], h2[j], v);
        v = __hfma2(c[3], h3[j], v);
        const float2 fv = __half22float2(v);
        acc[j].x = fmaf(wg, fv.x, acc[j].x);
        acc[j].y = fmaf(wg, fv.y, acc[j].y);
    }
}

// ---------------- Kernel 2: persistent gather, dynamic unit queue ----------
// 296 CTAs x 512 threads (16 warps, 2/SM — the proven R8/R11 shape). Work
// units = half-anchors (1800): eliminates the 3.04-wave scheduling tail.
// Per unit: metadata -> gather (2-sample interleave, 8 LDG.128 in flight)
// -> 16-warp reduce -> partial store; second finisher of an anchor combines
// the two partials in fixed order and writes the output.
__global__ __launch_bounds__(512, 2)
void daf_gather(const float* __restrict__ points,    // [1,900,13,6,2]
                const float* __restrict__ weights,   // [1,900,13,6,4,8]
                float* __restrict__ out)             // [1,900,256]
{
    const int tid  = threadIdx.x;
    const int warp = tid >> 5;
    const int lane = tid & 31;
    const int g    = lane >> 2;   // group of this lane's 8 channels

    __shared__ int4     s_idx[SPC];        // 4 corner row indices
    __shared__ uint4    s_cwh[SPC];        // 4 bilinear*valid weights as half2
    __shared__ float    s_w  [SPC][G_N];   // 8 group weights (fp32)
    __shared__ float    s_red[NWARP][CH];  // per-warp partials
    __shared__ unsigned s_unit;
    __shared__ unsigned s_last;

    if (tid == 0) s_unit = atomicAdd(&d_qhead, 1u);
    __syncthreads();
    unsigned unit = s_unit;
    bool first = true;

    while (unit < UNITS) {
        const int a   = unit >> 1;
        const int hlf = unit & 1;

        // ---------- metadata for this unit's 156 samples ----------
        if (tid < SPC) {
            const int s   = hlf * SPC + tid;
            const int pt  = s / (CAM_N * LVL_N);
            const int rem = s - pt * (CAM_N * LVL_N);
            const int cam = rem >> 2;            // / LVL_N
            const int lvl = rem & 3;             // % LVL_N

            const float2 p = *reinterpret_cast<const float2*>(
                points + (((size_t)a * P_N + pt) * CAM_N + cam) * 2);

            const int h = c_H[lvl], w = c_W[lvl];
            const float x = p.x * (float)w - 0.5f;
            const float y = p.y * (float)h - 0.5f;
            const float x0f = floorf(x), y0f = floorf(y);
            const int   x0  = (int)x0f,  y0  = (int)y0f;
            const float fx  = x - x0f,   fy  = y - y0f;
            const float wx[2] = {1.0f - fx, fx};
            const float wy[2] = {1.0f - fy, fy};
            const int base = cam * THW + c_S[lvl];

            int     vi[4];
            __half2 vc[4];
            #pragma unroll
            for (int k = 0; k < 4; k++) {
                const int dx = k & 1, dy = k >> 1;
                const int xi = x0 + dx, yi = y0 + dy;
                const bool valid = (xi >= 0) & (xi < w) & (yi >= 0) & (yi < h);
                const int xc = min(max(xi, 0), w - 1);
                const int yc = min(max(yi, 0), h - 1);
                vi[k] = base + yc * w + xc;
                vc[k] = __float2half2_rn(valid ? wx[dx] * wy[dy] : 0.0f);
            }
            s_idx[tid] = make_int4(vi[0], vi[1], vi[2], vi[3]);
            s_cwh[tid] = *reinterpret_cast<const uint4*>(vc);

            const float4* wp = reinterpret_cast<const float4*>(
                weights + ((((size_t)a * P_N + pt) * CAM_N + cam) * LVL_N + lvl) * G_N);
            float4* wd = reinterpret_cast<float4*>(&s_w[tid][0]);
            wd[0] = wp[0];
            wd[1] = wp[1];
        }
        __syncthreads();

        if (first) {
            // fp16 buffer must be complete before the first feature read.
            asm volatile("griddepcontrol.wait;" ::: "memory");
            first = false;
        }

        // ---------- gather + weighted accumulate ----------
        float2 acc[4] = {{0.f,0.f},{0.f,0.f},{0.f,0.f},{0.f,0.f}};

        int i = warp;
        for (; i + NWARP < SPC; i += 2 * NWARP) {
            const int j = i + NWARP;
            const int4 ia = s_idx[i];
            const int4 ib = s_idx[j];
            const uint4 pa0 = *(reinterpret_cast<const uint4*>(d_feath + (size_t)ia.x * CH) + lane);
            const uint4 pa1 = *(reinterpret_cast<const uint4*>(d_feath + (size_t)ia.y * CH) + lane);
            const uint4 pa2 = *(reinterpret_cast<const uint4*>(d_feath + (size_t)ia.z * CH) + lane);
            const uint4 pa3 = *(reinterpret_cast<const uint4*>(d_feath + (size_t)ia.w * CH) + lane);
            const uint4 pb0 = *(reinterpret_cast<const uint4*>(d_feath + (size_t)ib.x * CH) + lane);
            const uint4 pb1 = *(reinterpret_cast<const uint4*>(d_feath + (size_t)ib.y * CH) + lane);
            const uint4 pb2 = *(reinterpret_cast<const uint4*>(d_feath + (size_t)ib.z * CH) + lane);
            const uint4 pb3 = *(reinterpret_cast<const uint4*>(d_feath + (size_t)ib.w * CH) + lane);
            sample_acc(pa0, pa1, pa2, pa3, s_cwh[i], s_w[i][g], acc);
            sample_acc(pb0, pb1, pb2, pb3, s_cwh[j], s_w[j][g], acc);
        }
        if (i < SPC) {
            const int4 ia = s_idx[i];
            const uint4 pa0 = *(reinterpret_cast<const uint4*>(d_feath + (size_t)ia.x * CH) + lane);
            const uint4 pa1 = *(reinterpret_cast<const uint4*>(d_feath + (size_t)ia.y * CH) + lane);
            const uint4 pa2 = *(reinterpret_cast<const uint4*>(d_feath + (size_t)ia.z * CH) + lane);
            const uint4 pa3 = *(reinterpret_cast<const uint4*>(d_feath + (size_t)ia.w * CH) + lane);
            sample_acc(pa0, pa1, pa2, pa3, s_cwh[i], s_w[i][g], acc);
        }

        // ---------- reduce 16 warps, store partial ----------
        {
            float4* dst = reinterpret_cast<float4*>(&s_red[warp][lane * 8]);
            dst[0] = make_float4(acc[0].x, acc[0].y, acc[1].x, acc[1].y);
            dst[1] = make_float4(acc[2].x, acc[2].y, acc[3].x, acc[3].y);
        }
        __syncthreads();

        if (tid < 64) {
            float4 r = make_float4(0.f, 0.f, 0.f, 0.f);
            #pragma unroll
            for (int w = 0; w < NWARP; w++) {
                const float4 t = reinterpret_cast<const float4*>(&s_red[w][0])[tid];
                r.x += t.x; r.y += t.y; r.z += t.z; r.w += t.w;
            }
            reinterpret_cast<float4*>(
                d_partial + ((size_t)hlf * A_N + a) * CH)[tid] = r;
            __threadfence();   // make this unit's partial globally visible
        }
        __syncthreads();

        // ---------- second finisher combines both halves ----------
        if (tid == 0) s_last = atomicAdd(&d_ticket[a], 1u);
        __syncthreads();
        if (s_last == 1u) {
            if (tid < 64) {
                const float4* p0 = reinterpret_cast<const float4*>(d_partial + (size_t)a * CH);
                const float4* p1 = reinterpret_cast<const float4*>(d_partial + ((size_t)A_N + a) * CH);
                const float4 u = __ldcg(p0 + tid);   // fixed order: half0 + half1
                const float4 v = __ldcg(p1 + tid);
                float4 r;
                r.x = u.x + v.x;
                r.y = u.y + v.y;
                r.z = u.z + v.z;
                r.w = u.w + v.w;
                reinterpret_cast<float4*>(out + (size_t)a * CH)[tid] = r;
            }
            if (tid == 0) d_ticket[a] = 0;   // reset for the next replay
        }

        // ---------- grab next unit ----------
        __syncthreads();
        if (tid == 0) s_unit = atomicAdd(&d_qhead, 1u);
        __syncthreads();
        unit = s_unit;
    }

    // ---------- last CTA resets the queue for the next replay ----------
    if (tid == 0) {
        const unsigned t = atomicAdd(&d_done, 1u);
        if (t == GRID_G - 1) {
            d_qhead = 0;
            d_done  = 0;
        }
    }
}

extern "C" void kernel_launch(void* const* d_in, const int* in_sizes, int n_in,
                              void* d_out, int out_size)
{
    const float* feature = (const float*)d_in[0];
    // d_in[1] = spatial_shapes, d_in[2] = level_start_index (static, hardcoded)
    const float* points  = (const float*)d_in[3];
    const float* weights = (const float*)d_in[4];
    float* out = (float*)d_out;

    cvt_kernel<<<FEAT_N / 8 / 256, 256>>>(feature);

    // PDL: gather launches early; griddepcontrol.wait gates the fp16 reads.
    cudaLaunchConfig_t cfg = {};
    cfg.gridDim  = dim3(GRID_G);
    cfg.blockDim = dim3(512);
    cfg.stream   = 0;
    cudaLaunchAttribute attr[1];
    attr[0].id = cudaLaunchAttributeProgrammaticStreamSerialization;
    attr[0].val.programmaticStreamSerializationAllowed = 1;
    cfg.attrs = attr;
    cfg.numAttrs = 1;
    cudaLaunchKernelEx(&cfg, daf_gather, points, weights, out);
}

// round 15
// speedup vs baseline: 1.2507x; 1.2507x over previous
#include <cuda_runtime.h>
#include <cuda_fp16.h>
#include <cstdint>

// Problem constants (static per reference)
#define A_N    900      // anchors
#define P_N    13       // points
#define CAM_N  6        // cameras
#define LVL_N  4        // levels
#define CH     256      // channels
#define G_N    8        // groups (32 ch each)
#define SAMP   (P_N * CAM_N * LVL_N)   // 312 samples per anchor
#define PC     (P_N * CAM_N)           // 78 samples per level
#define THW    14960    // sum of H*W over levels
#define NWARP  16
#define FEAT_N (CAM_N * THW * CH)

// Level-1..3 region: rows [11264, 14960) per cam.
#define HI_ROW0   11264
#define HI_ROWS   3696
#define HI_FLOATS (CAM_N * HI_ROWS * CH)          // 5,677,056
#define CVT_CTAS  (HI_FLOATS / 8 / 256)           // 2772 exactly

__constant__ int c_H[LVL_N] = {64, 32, 16, 8};
__constant__ int c_W[LVL_N] = {176, 88, 44, 22};
__constant__ int c_S[LVL_N] = {0, 11264, 14080, 14784};

// fp16 copy of levels 1-3 only (stored at absolute row offsets; level-0
// region of this buffer is never written or read).
__device__ __half d_feath[FEAT_N];

// ---------------- Kernel 1: fp32 -> fp16, LEVELS 1-3 ONLY (23 MB) ----------
__global__ __launch_bounds__(256)
void cvt_kernel(const float* __restrict__ f)
{
    asm volatile("griddepcontrol.launch_dependents;" ::: "memory");
    const unsigned t   = blockIdx.x * 256 + threadIdx.x;
    const unsigned per = HI_ROWS * CH / 8;        // units per cam (118272)
    const unsigned cam = t / per;
    const unsigned off = t - cam * per;
    const size_t i = ((size_t)cam * THW + HI_ROW0) * CH + (size_t)off * 8;

    const float4 a = __ldcs(reinterpret_cast<const float4*>(f + i));
    const float4 b = __ldcs(reinterpret_cast<const float4*>(f + i + 4));
    __half2 h[4];
    h[0] = __floats2half2_rn(a.x, a.y);
    h[1] = __floats2half2_rn(a.z, a.w);
    h[2] = __floats2half2_rn(b.x, b.y);
    h[3] = __floats2half2_rn(b.z, b.w);
    *reinterpret_cast<uint4*>(d_feath + i) = *reinterpret_cast<const uint4*>(h);
}

// fp16 sample: bilinear in HFMA2 (pre-packed half2 corner weights), fp32 FMA
// applies the group weight into the fp32 accumulator (R11 math).
__device__ __forceinline__ void sample_acc_h(
    const uint4& u0, const uint4& u1, const uint4& u2, const uint4& u3,
    const uint4& cwp, const float wg, float2* acc)
{
    const __half2* c  = reinterpret_cast<const __half2*>(&cwp);
    const __half2* h0 = reinterpret_cast<const __half2*>(&u0);
    const __half2* h1 = reinterpret_cast<const __half2*>(&u1);
    const __half2* h2 = reinterpret_cast<const __half2*>(&u2);
    const __half2* h3 = reinterpret_cast<const __half2*>(&u3);
    #pragma unroll
    for (int j = 0; j < 4; j++) {
        __half2 v = __hmul2(c[0], h0[j]);
        v = __hfma2(c[1], h1[j], v);
        v = __hfma2(c[2], h2[j], v);
        v = __hfma2(c[3], h3[j], v);
        const float2 fv = __half22float2(v);
        acc[j].x = fmaf(wg, fv.x, acc[j].x);
        acc[j].y = fmaf(wg, fv.y, acc[j].y);
    }
}

// ---------------- Kernel 2: gather ----------------
// One CTA per anchor, 512 threads = 16 warps. Sample slots level-major
// {0,1,2,3}: slots [0,78) = level 0, gathered in fp32 from the ORIGINAL
// feature (exact, R4 burst shape) BEFORE the PDL wait -> overlaps cvt;
// slots [78,312) = levels 1-3, fp16 HFMA2 path after the wait.
__global__ __launch_bounds__(512, 2)
void daf_gather(const float* __restrict__ feature,   // [1,6,14960,256] fp32
                const float* __restrict__ points,    // [1,900,13,6,2]
                const float* __restrict__ weights,   // [1,900,13,6,4,8]
                float* __restrict__ out)             // [1,900,256]
{
    const int a   = blockIdx.x;
    const int tid = threadIdx.x;

    __shared__ int4   s_idx[SAMP];       // 4 corner row indices
    __shared__ float4 s_cwf[PC];         // fp32 corner weights (level 0)
    __shared__ uint4  s_cwh[SAMP];       // half2 corner weights (levels 1-3)
    __shared__ float  s_w  [SAMP][G_N];  // 8 group weights (fp32)
    __shared__ float  s_red[NWARP][CH];  // per-warp partials

    // ---------- Phase 1: per-sample metadata ----------
    if (tid < SAMP) {
        const int s      = tid;
        const int lvl    = s / PC;          // level-major order 0,1,2,3
        const int within = s - lvl * PC;
        const int pt     = within / CAM_N;
        const int cam    = within - pt * CAM_N;

        const float2 p = *reinterpret_cast<const float2*>(
            points + (((size_t)a * P_N + pt) * CAM_N + cam) * 2);

        const int h = c_H[lvl], w = c_W[lvl];
        const float x = p.x * (float)w - 0.5f;
        const float y = p.y * (float)h - 0.5f;
        const float x0f = floorf(x), y0f = floorf(y);
        const int   x0  = (int)x0f,  y0  = (int)y0f;
        const float fx  = x - x0f,   fy  = y - y0f;
        const float wx[2] = {1.0f - fx, fx};
        const float wy[2] = {1.0f - fy, fy};
        const int base = cam * THW + c_S[lvl];

        int   vi[4];
        float vc[4];
        #pragma unroll
        for (int k = 0; k < 4; k++) {
            const int dx = k & 1, dy = k >> 1;
            const int xi = x0 + dx, yi = y0 + dy;
            const bool valid = (xi >= 0) & (xi < w) & (yi >= 0) & (yi < h);
            const int xc = min(max(xi, 0), w - 1);
            const int yc = min(max(yi, 0), h - 1);
            vi[k] = base + yc * w + xc;
            vc[k] = valid ? wx[dx] * wy[dy] : 0.0f;
        }
        s_idx[s] = make_int4(vi[0], vi[1], vi[2], vi[3]);
        if (lvl == 0) {
            s_cwf[s] = make_float4(vc[0], vc[1], vc[2], vc[3]);
        } else {
            __half2 hc[4];
            #pragma unroll
            for (int k = 0; k < 4; k++) hc[k] = __float2half2_rn(vc[k]);
            s_cwh[s] = *reinterpret_cast<const uint4*>(hc);
        }

        const float4* wp = reinterpret_cast<const float4*>(
            weights + ((((size_t)a * P_N + pt) * CAM_N + cam) * LVL_N + lvl) * G_N);
        float4* wd = reinterpret_cast<float4*>(&s_w[s][0]);
        wd[0] = wp[0];
        wd[1] = wp[1];
    }
    __syncthreads();

    const int warp = tid >> 5;
    const int lane = tid & 31;

    // ---------- Phase A: level 0 in fp32 (overlaps cvt) ----------
    // R4 layout: lane owns channel quads [lane*4,..) and [128+lane*4,..).
    {
        const int g4 = lane >> 3;             // group of quad A (quad B: 4+g4)
        float4 accA = make_float4(0.f, 0.f, 0.f, 0.f);
        float4 accB = make_float4(0.f, 0.f, 0.f, 0.f);

        for (int i = warp; i < PC; i += NWARP) {
            const int4   idx = s_idx[i];
            const float4 cw  = s_cwf[i];
            const float  wgA = s_w[i][g4];
            const float  wgB = s_w[i][4 + g4];

            const float4* r0 = reinterpret_cast<const float4*>(feature + (size_t)idx.x * CH) + lane;
            const float4* r1 = reinterpret_cast<const float4*>(feature + (size_t)idx.y * CH) + lane;
            const float4* r2 = reinterpret_cast<const float4*>(feature + (size_t)idx.z * CH) + lane;
            const float4* r3 = reinterpret_cast<const float4*>(feature + (size_t)idx.w * CH) + lane;

            const float4 a0 = r0[0],  b0 = r0[32];
            const float4 a1 = r1[0],  b1 = r1[32];
            const float4 a2 = r2[0],  b2 = r2[32];
            const float4 a3 = r3[0],  b3 = r3[32];

            accA.x += wgA * (cw.x*a0.x + cw.y*a1.x + cw.z*a2.x + cw.w*a3.x);
            accA.y += wgA * (cw.x*a0.y + cw.y*a1.y + cw.z*a2.y + cw.w*a3.y);
            accA.z += wgA * (cw.x*a0.z + cw.y*a1.z + cw.z*a2.z + cw.w*a3.z);
            accA.w += wgA * (cw.x*a0.w + cw.y*a1.w + cw.z*a2.w + cw.w*a3.w);
            accB.x += wgB * (cw.x*b0.x + cw.y*b1.x + cw.z*b2.x + cw.w*b3.x);
            accB.y += wgB * (cw.x*b0.y + cw.y*b1.y + cw.z*b2.y + cw.w*b3.y);
            accB.z += wgB * (cw.x*b0.z + cw.y*b1.z + cw.z*b2.z + cw.w*b3.z);
            accB.w += wgB * (cw.x*b0.w + cw.y*b1.w + cw.z*b2.w + cw.w*b3.w);
        }
        // Seed s_red with the level-0 partial (R4 placement).
        float4* row = reinterpret_cast<float4*>(&s_red[warp][0]);
        row[lane]      = accA;
        row[32 + lane] = accB;
    }
    __syncwarp();

    // ---------- Phase B: levels 1-3 in fp16 (after cvt completes) ----------
    asm volatile("griddepcontrol.wait;" ::: "memory");
    {
        const int g = lane >> 2;              // group of lane's 8 channels
        float2 acc[4] = {{0.f,0.f},{0.f,0.f},{0.f,0.f},{0.f,0.f}};

        int i = PC + warp;
        for (; i + NWARP < SAMP; i += 2 * NWARP) {
            const int j = i + NWARP;
            const int4 ia = s_idx[i];
            const int4 ib = s_idx[j];
            const uint4 pa0 = *(reinterpret_cast<const uint4*>(d_feath + (size_t)ia.x * CH) + lane);
            const uint4 pa1 = *(reinterpret_cast<const uint4*>(d_feath + (size_t)ia.y * CH) + lane);
            const uint4 pa2 = *(reinterpret_cast<const uint4*>(d_feath + (size_t)ia.z * CH) + lane);
            const uint4 pa3 = *(reinterpret_cast<const uint4*>(d_feath + (size_t)ia.w * CH) + lane);
            const uint4 pb0 = *(reinterpret_cast<const uint4*>(d_feath + (size_t)ib.x * CH) + lane);
            const uint4 pb1 = *(reinterpret_cast<const uint4*>(d_feath + (size_t)ib.y * CH) + lane);
            const uint4 pb2 = *(reinterpret_cast<const uint4*>(d_feath + (size_t)ib.z * CH) + lane);
            const uint4 pb3 = *(reinterpret_cast<const uint4*>(d_feath + (size_t)ib.w * CH) + lane);
            sample_acc_h(pa0, pa1, pa2, pa3, s_cwh[i], s_w[i][g], acc);
            sample_acc_h(pb0, pb1, pb2, pb3, s_cwh[j], s_w[j][g], acc);
        }
        if (i < SAMP) {
            const int4 ia = s_idx[i];
            const uint4 pa0 = *(reinterpret_cast<const uint4*>(d_feath + (size_t)ia.x * CH) + lane);
            const uint4 pa1 = *(reinterpret_cast<const uint4*>(d_feath + (size_t)ia.y * CH) + lane);
            const uint4 pa2 = *(reinterpret_cast<const uint4*>(d_feath + (size_t)ia.z * CH) + lane);
            const uint4 pa3 = *(reinterpret_cast<const uint4*>(d_feath + (size_t)ia.w * CH) + lane);
            sample_acc_h(pa0, pa1, pa2, pa3, s_cwh[i], s_w[i][g], acc);
        }

        // Add the fp16-phase partial into this warp's s_red row
        // (lane owns channels [lane*8, lane*8+8) here).
        float4* row = reinterpret_cast<float4*>(&s_red[warp][0]);
        float4 r0 = row[lane * 2];
        float4 r1 = row[lane * 2 + 1];
        r0.x += acc[0].x;  r0.y += acc[0].y;  r0.z += acc[1].x;  r0.w += acc[1].y;
        r1.x += acc[2].x;  r1.y += acc[2].y;  r1.z += acc[3].x;  r1.w += acc[3].y;
        row[lane * 2]     = r0;
        row[lane * 2 + 1] = r1;
    }
    __syncthreads();

    // ---------- Phase 3: reduce 16 warps, write output ----------
    if (tid < 64) {
        float4 r = make_float4(0.f, 0.f, 0.f, 0.f);
        #pragma unroll
        for (int w = 0; w < NWARP; w++) {
            const float4 t = reinterpret_cast<const float4*>(&s_red[w][0])[tid];
            r.x += t.x; r.y += t.y; r.z += t.z; r.w += t.w;
        }
        reinterpret_cast<float4*>(out + (size_t)a * CH)[tid] = r;
    }
}

extern "C" void kernel_launch(void* const* d_in, const int* in_sizes, int n_in,
                              void* d_out, int out_size)
{
    const float* feature = (const float*)d_in[0];
    // d_in[1] = spatial_shapes, d_in[2] = level_start_index (static, hardcoded)
    const float* points  = (const float*)d_in[3];
    const float* weights = (const float*)d_in[4];
    float* out = (float*)d_out;

    cvt_kernel<<<CVT_CTAS, 256>>>(feature);

    // PDL: gather starts early; its level-0 fp32 phase needs no conversion
    // and overlaps cvt; griddepcontrol.wait gates the fp16 reads only.
    cudaLaunchConfig_t cfg = {};
    cfg.gridDim  = dim3(A_N);
    cfg.blockDim = dim3(512);
    cfg.stream   = 0;
    cudaLaunchAttribute attr[1];
    attr[0].id = cudaLaunchAttributeProgrammaticStreamSerialization;
    attr[0].val.programmaticStreamSerializationAllowed = 1;
    cfg.attrs = attr;
    cfg.numAttrs = 1;
    cudaLaunchKernelEx(&cfg, daf_gather, feature, points, weights, out);
}

// round 16
// speedup vs baseline: 1.2582x; 1.0061x over previous
#include <cuda_runtime.h>
#include <cuda_fp16.h>
#include <cstdint>

// Problem constants (static per reference)
#define A_N    900      // anchors
#define P_N    13       // points
#define CAM_N  6        // cameras
#define LVL_N  4        // levels
#define CH     256      // channels
#define G_N    8        // groups (32 ch each)
#define SAMP   (P_N * CAM_N * LVL_N)   // 312 samples per anchor
#define PC     (P_N * CAM_N)           // 78 samples per level
#define THW    14960    // sum of H*W over levels
#define NWARP  16
#define FEAT_N (CAM_N * THW * CH)

// Level-1..3 region: rows [11264, 14960) per cam.
#define HI_ROW0   11264
#define HI_ROWS   3696
#define HI_FLOATS (CAM_N * HI_ROWS * CH)          // 5,677,056
#define CVT_CTAS  (HI_FLOATS / 8 / 256)           // 2772 exactly

__constant__ int c_H[LVL_N] = {64, 32, 16, 8};
__constant__ int c_W[LVL_N] = {176, 88, 44, 22};
__constant__ int c_S[LVL_N] = {0, 11264, 14080, 14784};

// fp16 copy of levels 1-3 only (level-0 region never touched).
__device__ __half d_feath[FEAT_N];

// ---------------- Kernel 1: fp32 -> fp16, LEVELS 1-3 ONLY (23 MB) ----------
__global__ __launch_bounds__(256)
void cvt_kernel(const float* __restrict__ f)
{
    asm volatile("griddepcontrol.launch_dependents;" ::: "memory");
    const unsigned t   = blockIdx.x * 256 + threadIdx.x;
    const unsigned per = HI_ROWS * CH / 8;        // units per cam (118272)
    const unsigned cam = t / per;
    const unsigned off = t - cam * per;
    const size_t i = ((size_t)cam * THW + HI_ROW0) * CH + (size_t)off * 8;

    const float4 a = __ldcs(reinterpret_cast<const float4*>(f + i));
    const float4 b = __ldcs(reinterpret_cast<const float4*>(f + i + 4));
    __half2 h[4];
    h[0] = __floats2half2_rn(a.x, a.y);
    h[1] = __floats2half2_rn(a.z, a.w);
    h[2] = __floats2half2_rn(b.x, b.y);
    h[3] = __floats2half2_rn(b.z, b.w);
    *reinterpret_cast<uint4*>(d_feath + i) = *reinterpret_cast<const uint4*>(h);
}

// fp32 sample contribution for one channel quad (Phase A).
__device__ __forceinline__ void sample_acc_f(
    const float4& a0, const float4& a1, const float4& a2, const float4& a3,
    const float4 cw, const float wg, float4& acc)
{
    acc.x += wg * (cw.x*a0.x + cw.y*a1.x + cw.z*a2.x + cw.w*a3.x);
    acc.y += wg * (cw.x*a0.y + cw.y*a1.y + cw.z*a2.y + cw.w*a3.y);
    acc.z += wg * (cw.x*a0.z + cw.y*a1.z + cw.z*a2.z + cw.w*a3.z);
    acc.w += wg * (cw.x*a0.w + cw.y*a1.w + cw.z*a2.w + cw.w*a3.w);
}

// fp16 sample: bilinear in HFMA2 (pre-packed half2 corner weights), fp32 FMA
// applies the group weight into the fp32 accumulator (R11 math).
__device__ __forceinline__ void sample_acc_h(
    const uint4& u0, const uint4& u1, const uint4& u2, const uint4& u3,
    const uint4& cwp, const float wg, float2* acc)
{
    const __half2* c  = reinterpret_cast<const __half2*>(&cwp);
    const __half2* h0 = reinterpret_cast<const __half2*>(&u0);
    const __half2* h1 = reinterpret_cast<const __half2*>(&u1);
    const __half2* h2 = reinterpret_cast<const __half2*>(&u2);
    const __half2* h3 = reinterpret_cast<const __half2*>(&u3);
    #pragma unroll
    for (int j = 0; j < 4; j++) {
        __half2 v = __hmul2(c[0], h0[j]);
        v = __hfma2(c[1], h1[j], v);
        v = __hfma2(c[2], h2[j], v);
        v = __hfma2(c[3], h3[j], v);
        const float2 fv = __half22float2(v);
        acc[j].x = fmaf(wg, fv.x, acc[j].x);
        acc[j].y = fmaf(wg, fv.y, acc[j].y);
    }
}

// ---------------- Kernel 2: gather ----------------
// One CTA per anchor, 512 threads = 16 warps. Slots [0,78) = level 0 in fp32
// from the ORIGINAL feature (exact) BEFORE the PDL wait -> overlaps cvt;
// slots [78,312) = levels 1-3 in fp16 after the wait.
// Phase A density fix: warp pairs split the 1KB fp32 row (warp>>3 = channel
// half), so the 8-load in-flight window retires 2 samples (same as Phase B).
__global__ __launch_bounds__(512, 2)
void daf_gather(const float* __restrict__ feature,   // [1,6,14960,256] fp32
                const float* __restrict__ points,    // [1,900,13,6,2]
                const float* __restrict__ weights,   // [1,900,13,6,4,8]
                float* __restrict__ out)             // [1,900,256]
{
    const int a   = blockIdx.x;
    const int tid = threadIdx.x;

    __shared__ int4   s_idx[SAMP];       // 4 corner row indices
    __shared__ float4 s_cwf[PC];         // fp32 corner weights (level 0)
    __shared__ uint4  s_cwh[SAMP];       // half2 corner weights (levels 1-3)
    __shared__ float  s_w  [SAMP][G_N];  // 8 group weights (fp32)
    __shared__ float  s_red[NWARP][CH];  // per-warp partials

    // ---------- Phase 1: per-sample metadata ----------
    if (tid < SAMP) {
        const int s      = tid;
        const int lvl    = s / PC;          // level-major order 0,1,2,3
        const int within = s - lvl * PC;
        const int pt     = within / CAM_N;
        const int cam    = within - pt * CAM_N;

        const float2 p = *reinterpret_cast<const float2*>(
            points + (((size_t)a * P_N + pt) * CAM_N + cam) * 2);

        const int h = c_H[lvl], w = c_W[lvl];
        const float x = p.x * (float)w - 0.5f;
        const float y = p.y * (float)h - 0.5f;
        const float x0f = floorf(x), y0f = floorf(y);
        const int   x0  = (int)x0f,  y0  = (int)y0f;
        const float fx  = x - x0f,   fy  = y - y0f;
        const float wx[2] = {1.0f - fx, fx};
        const float wy[2] = {1.0f - fy, fy};
        const int base = cam * THW + c_S[lvl];

        int   vi[4];
        float vc[4];
        #pragma unroll
        for (int k = 0; k < 4; k++) {
            const int dx = k & 1, dy = k >> 1;
            const int xi = x0 + dx, yi = y0 + dy;
            const bool valid = (xi >= 0) & (xi < w) & (yi >= 0) & (yi < h);
            const int xc = min(max(xi, 0), w - 1);
            const int yc = min(max(yi, 0), h - 1);
            vi[k] = base + yc * w + xc;
            vc[k] = valid ? wx[dx] * wy[dy] : 0.0f;
        }
        s_idx[s] = make_int4(vi[0], vi[1], vi[2], vi[3]);
        if (lvl == 0) {
            s_cwf[s] = make_float4(vc[0], vc[1], vc[2], vc[3]);
        } else {
            __half2 hc[4];
            #pragma unroll
            for (int k = 0; k < 4; k++) hc[k] = __float2half2_rn(vc[k]);
            s_cwh[s] = *reinterpret_cast<const uint4*>(hc);
        }

        const float4* wp = reinterpret_cast<const float4*>(
            weights + ((((size_t)a * P_N + pt) * CAM_N + cam) * LVL_N + lvl) * G_N);
        float4* wd = reinterpret_cast<float4*>(&s_w[s][0]);
        wd[0] = wp[0];
        wd[1] = wp[1];
    }
    __syncthreads();

    const int warp = tid >> 5;
    const int lane = tid & 31;

    // ---------- Phase A: level 0 in fp32 (overlaps cvt) ----------
    // warp pairs (sub, sub+8) split the row: half = warp>>3 owns channels
    // [half*128, half*128+128); lane owns quad cidx = half*32+lane.
    {
        const int sub  = warp & 7;            // sample lane (8 sample slots)
        const int half = warp >> 3;           // channel half
        const int cidx = half * 32 + lane;    // float4 index into row
        const int g4   = half * 4 + (lane >> 3);

        float4 acc = make_float4(0.f, 0.f, 0.f, 0.f);

        int i = sub;
        for (; i + 8 < PC; i += 16) {
            const int j = i + 8;
            const int4 ia = s_idx[i];
            const int4 ib = s_idx[j];

            // 8 independent LDG.128 covering TWO samples' 4 corners (this half)
            const float4 a0 = *(reinterpret_cast<const float4*>(feature + (size_t)ia.x * CH) + cidx);
            const float4 a1 = *(reinterpret_cast<const float4*>(feature + (size_t)ia.y * CH) + cidx);
            const float4 a2 = *(reinterpret_cast<const float4*>(feature + (size_t)ia.z * CH) + cidx);
            const float4 a3 = *(reinterpret_cast<const float4*>(feature + (size_t)ia.w * CH) + cidx);
            const float4 b0 = *(reinterpret_cast<const float4*>(feature + (size_t)ib.x * CH) + cidx);
            const float4 b1 = *(reinterpret_cast<const float4*>(feature + (size_t)ib.y * CH) + cidx);
            const float4 b2 = *(reinterpret_cast<const float4*>(feature + (size_t)ib.z * CH) + cidx);
            const float4 b3 = *(reinterpret_cast<const float4*>(feature + (size_t)ib.w * CH) + cidx);

            sample_acc_f(a0, a1, a2, a3, s_cwf[i], s_w[i][g4], acc);
            sample_acc_f(b0, b1, b2, b3, s_cwf[j], s_w[j][g4], acc);
        }
        if (i < PC) {
            const int4 ia = s_idx[i];
            const float4 a0 = *(reinterpret_cast<const float4*>(feature + (size_t)ia.x * CH) + cidx);
            const float4 a1 = *(reinterpret_cast<const float4*>(feature + (size_t)ia.y * CH) + cidx);
            const float4 a2 = *(reinterpret_cast<const float4*>(feature + (size_t)ia.z * CH) + cidx);
            const float4 a3 = *(reinterpret_cast<const float4*>(feature + (size_t)ia.w * CH) + cidx);
            sample_acc_f(a0, a1, a2, a3, s_cwf[i], s_w[i][g4], acc);
        }

        // Seed this warp's s_red row: own half = acc, other half = 0.
        float4* row = reinterpret_cast<float4*>(&s_red[warp][0]);
        row[cidx] = acc;
        row[(half ^ 1) * 32 + lane] = make_float4(0.f, 0.f, 0.f, 0.f);
    }
    __syncwarp();

    // ---------- Phase B: levels 1-3 in fp16 (after cvt completes) ----------
    asm volatile("griddepcontrol.wait;" ::: "memory");
    {
        const int g = lane >> 2;              // group of lane's 8 channels
        float2 acc[4] = {{0.f,0.f},{0.f,0.f},{0.f,0.f},{0.f,0.f}};

        int i = PC + warp;
        for (; i + NWARP < SAMP; i += 2 * NWARP) {
            const int j = i + NWARP;
            const int4 ia = s_idx[i];
            const int4 ib = s_idx[j];
            const uint4 pa0 = *(reinterpret_cast<const uint4*>(d_feath + (size_t)ia.x * CH) + lane);
            const uint4 pa1 = *(reinterpret_cast<const uint4*>(d_feath + (size_t)ia.y * CH) + lane);
            const uint4 pa2 = *(reinterpret_cast<const uint4*>(d_feath + (size_t)ia.z * CH) + lane);
            const uint4 pa3 = *(reinterpret_cast<const uint4*>(d_feath + (size_t)ia.w * CH) + lane);
            const uint4 pb0 = *(reinterpret_cast<const uint4*>(d_feath + (size_t)ib.x * CH) + lane);
            const uint4 pb1 = *(reinterpret_cast<const uint4*>(d_feath + (size_t)ib.y * CH) + lane);
            const uint4 pb2 = *(reinterpret_cast<const uint4*>(d_feath + (size_t)ib.z * CH) + lane);
            const uint4 pb3 = *(reinterpret_cast<const uint4*>(d_feath + (size_t)ib.w * CH) + lane);
            sample_acc_h(pa0, pa1, pa2, pa3, s_cwh[i], s_w[i][g], acc);
            sample_acc_h(pb0, pb1, pb2, pb3, s_cwh[j], s_w[j][g], acc);
        }
        if (i < SAMP) {
            const int4 ia = s_idx[i];
            const uint4 pa0 = *(reinterpret_cast<const uint4*>(d_feath + (size_t)ia.x * CH) + lane);
            const uint4 pa1 = *(reinterpret_cast<const uint4*>(d_feath + (size_t)ia.y * CH) + lane);
            const uint4 pa2 = *(reinterpret_cast<const uint4*>(d_feath + (size_t)ia.z * CH) + lane);
            const uint4 pa3 = *(reinterpret_cast<const uint4*>(d_feath + (size_t)ia.w * CH) + lane);
            sample_acc_h(pa0, pa1, pa2, pa3, s_cwh[i], s_w[i][g], acc);
        }

        // Add the fp16-phase partial into this warp's s_red row
        // (lane owns channels [lane*8, lane*8+8) here).
        float4* row = reinterpret_cast<float4*>(&s_red[warp][0]);
        float4 r0 = row[lane * 2];
        float4 r1 = row[lane * 2 + 1];
        r0.x += acc[0].x;  r0.y += acc[0].y;  r0.z += acc[1].x;  r0.w += acc[1].y;
        r1.x += acc[2].x;  r1.y += acc[2].y;  r1.z += acc[3].x;  r1.w += acc[3].y;
        row[lane * 2]     = r0;
        row[lane * 2 + 1] = r1;
    }
    __syncthreads();

    // ---------- Phase 3: reduce 16 warps, write output ----------
    if (tid < 64) {
        float4 r = make_float4(0.f, 0.f, 0.f, 0.f);
        #pragma unroll
        for (int w = 0; w < NWARP; w++) {
            const float4 t = reinterpret_cast<const float4*>(&s_red[w][0])[tid];
            r.x += t.x; r.y += t.y; r.z += t.z; r.w += t.w;
        }
        reinterpret_cast<float4*>(out + (size_t)a * CH)[tid] = r;
    }
}

extern "C" void kernel_launch(void* const* d_in, const int* in_sizes, int n_in,
                              void* d_out, int out_size)
{
    const float* feature = (const float*)d_in[0];
    // d_in[1] = spatial_shapes, d_in[2] = level_start_index (static, hardcoded)
    const float* points  = (const float*)d_in[3];
    const float* weights = (const float*)d_in[4];
    float* out = (float*)d_out;

    cvt_kernel<<<CVT_CTAS, 256>>>(feature);

    // PDL: gather starts early; its level-0 fp32 phase needs no conversion
    // and overlaps cvt; griddepcontrol.wait gates the fp16 reads only.
    cudaLaunchConfig_t cfg = {};
    cfg.gridDim  = dim3(A_N);
    cfg.blockDim = dim3(512);
    cfg.stream   = 0;
    cudaLaunchAttribute attr[1];
    attr[0].id = cudaLaunchAttributeProgrammaticStreamSerialization;
    attr[0].val.programmaticStreamSerializationAllowed = 1;
    cfg.attrs = attr;
    cfg.numAttrs = 1;
    cudaLaunchKernelEx(&cfg, daf_gather, feature, points, weights, out);
}